// round 1
// baseline (speedup 1.0000x reference)
#include <cuda_runtime.h>
#include <cuda_bf16.h>
#include <cstdint>

// ---------------------------------------------------------------------------
// SpatialAttention: out = proj( softmax(QK^T/sqrt(hd)) V ) for 16 folded
// batches, N=1024 tokens, D=512, H=8 heads, hd=64. All fp32.
//
// Pipeline:
//   K1: g_qkv[16384,1536] = X[16384,512] @ W_qkv + b_qkv      (SGEMM+bias)
//   K2: g_attn[16384,512] = flash-attention over g_qkv        (fp32 online softmax)
//   K3: out[16384,512]    = g_attn @ W_proj + b_proj          (SGEMM+bias)
// ---------------------------------------------------------------------------

#define BT_TOTAL 16
#define NTOK     1024
#define DMODEL   512
#define NHEADS   8
#define HD       64
#define MROWS    (BT_TOTAL * NTOK)      // 16384
#define QKV_COLS (3 * DMODEL)           // 1536

// Scratch (allocation-free: device globals)
__device__ float g_qkv[(size_t)MROWS * QKV_COLS];   // ~100.7 MB
__device__ float g_attn[(size_t)MROWS * DMODEL];    // ~33.5 MB

// ---------------------------------------------------------------------------
// SGEMM with fused bias: C[M,N] = A[M,K] @ B[K,N] + bias[N]
// Block tile 128x128, K-tile 8, 256 threads, 8x8 register micro-tile.
// Requires M%128==0, N%128==0, K%8==0 (true for all our shapes).
// ---------------------------------------------------------------------------
__global__ __launch_bounds__(256, 2)
void sgemm_bias(const float* __restrict__ A, const float* __restrict__ B,
                const float* __restrict__ bias, float* __restrict__ C,
                int M, int N, int K)
{
    __shared__ float As[8][128];   // As[k][m] (transposed A tile)
    __shared__ float Bs[8][128];   // Bs[k][n]

    const int t  = threadIdx.x;
    const int bm = blockIdx.y * 128;
    const int bn = blockIdx.x * 128;
    const int tx = t & 15;          // 0..15  -> n micro
    const int ty = t >> 4;          // 0..15  -> m micro

    const int arow = t >> 1;              // 0..127
    const int acol = (t & 1) << 2;        // 0 or 4
    const int brow = t >> 5;              // 0..7
    const int bcol = (t & 31) << 2;       // 0..124

    const float* Ag = A + (size_t)(bm + arow) * K + acol;
    const float* Bg = B + (size_t)brow * N + bn + bcol;

    float acc[8][8];
    #pragma unroll
    for (int i = 0; i < 8; ++i)
        #pragma unroll
        for (int j = 0; j < 8; ++j) acc[i][j] = 0.f;

    for (int k0 = 0; k0 < K; k0 += 8) {
        float4 av = *(const float4*)(Ag + k0);
        float4 bv = *(const float4*)(Bg + (size_t)k0 * N);

        As[acol + 0][arow] = av.x;
        As[acol + 1][arow] = av.y;
        As[acol + 2][arow] = av.z;
        As[acol + 3][arow] = av.w;
        *(float4*)&Bs[brow][bcol] = bv;
        __syncthreads();

        #pragma unroll
        for (int kk = 0; kk < 8; ++kk) {
            float ar[8], br[8];
            *(float4*)&ar[0] = *(const float4*)&As[kk][ty * 8];
            *(float4*)&ar[4] = *(const float4*)&As[kk][ty * 8 + 4];
            *(float4*)&br[0] = *(const float4*)&Bs[kk][tx * 8];
            *(float4*)&br[4] = *(const float4*)&Bs[kk][tx * 8 + 4];
            #pragma unroll
            for (int i = 0; i < 8; ++i)
                #pragma unroll
                for (int j = 0; j < 8; ++j)
                    acc[i][j] += ar[i] * br[j];
        }
        __syncthreads();
    }

    #pragma unroll
    for (int i = 0; i < 8; ++i) {
        const size_t row = (size_t)(bm + ty * 8 + i);
        #pragma unroll
        for (int j = 0; j < 8; j += 4) {
            const int col = bn + tx * 8 + j;
            float4 v;
            v.x = acc[i][j + 0] + bias[col + 0];
            v.y = acc[i][j + 1] + bias[col + 1];
            v.z = acc[i][j + 2] + bias[col + 2];
            v.w = acc[i][j + 3] + bias[col + 3];
            *(float4*)&C[row * N + col] = v;
        }
    }
}

// ---------------------------------------------------------------------------
// Flash attention (fp32, online softmax).
// grid = (16 row-blocks, 128 (bt,h) pairs), 256 threads.
// Each CTA: 64 query rows x full 1024 keys in 16 tiles of 64.
// Thread (ty=t>>4, tx=t&15) owns S/O micro-tile rows 4*ty..+3, cols 4*tx..+3.
// SMEM: QsT[d][r], KsT[d][j] (d-major for conflict-free S phase), Vs[j][d],
//       Ps[r][j]. Row stride 68 floats (pad).
// ---------------------------------------------------------------------------
#define FA_STR 68
#define FA_SMEM_FLOATS (4 * 64 * FA_STR)
#define FA_SMEM_BYTES  (FA_SMEM_FLOATS * 4)

__global__ __launch_bounds__(256, 3)
void flash_attn_kernel()
{
    const int rb = blockIdx.x;          // 0..15 query row block
    const int p  = blockIdx.y;          // 0..127 = bt*8 + h
    const int bt = p >> 3;
    const int h  = p & 7;

    extern __shared__ float sm[];
    float* QsT = sm;                    // [64][FA_STR]  QsT[d][r]
    float* KsT = sm + 64 * FA_STR;      // [64][FA_STR]  KsT[d][j]
    float* Vs  = sm + 2 * 64 * FA_STR;  // [64][FA_STR]  Vs[j][d]
    float* Ps  = sm + 3 * 64 * FA_STR;  // [64][FA_STR]  Ps[r][j]

    const int t  = threadIdx.x;
    const int tx = t & 15;
    const int ty = t >> 4;
    const int li = t >> 2;              // 0..63 tile row for loads
    const int lc = (t & 3) << 4;        // 0,16,32,48 tile col base

    const size_t base = (size_t)bt * NTOK * QKV_COLS;
    const float scale = 0.125f;         // 1/sqrt(64)

    // Load Q tile transposed (and pre-scaled)
    {
        const float* qrow = g_qkv + base + (size_t)(rb * 64 + li) * QKV_COLS + h * HD + lc;
        #pragma unroll
        for (int u = 0; u < 4; ++u) {
            float4 v = *(const float4*)(qrow + u * 4);
            const int c = lc + u * 4;
            QsT[(c + 0) * FA_STR + li] = v.x * scale;
            QsT[(c + 1) * FA_STR + li] = v.y * scale;
            QsT[(c + 2) * FA_STR + li] = v.z * scale;
            QsT[(c + 3) * FA_STR + li] = v.w * scale;
        }
    }

    float m[4], l[4], o[4][4];
    #pragma unroll
    for (int i = 0; i < 4; ++i) {
        m[i] = -1e30f;
        l[i] = 0.f;
        #pragma unroll
        for (int j = 0; j < 4; ++j) o[i][j] = 0.f;
    }

    for (int kb = 0; kb < 16; ++kb) {
        __syncthreads();   // prev PV done (and first-iter Q stores ordered)

        // Load K tile (transposed) and V tile
        {
            const float* krow = g_qkv + base + (size_t)(kb * 64 + li) * QKV_COLS
                                + DMODEL + h * HD + lc;
            #pragma unroll
            for (int u = 0; u < 4; ++u) {
                float4 v = *(const float4*)(krow + u * 4);
                const int c = lc + u * 4;
                KsT[(c + 0) * FA_STR + li] = v.x;
                KsT[(c + 1) * FA_STR + li] = v.y;
                KsT[(c + 2) * FA_STR + li] = v.z;
                KsT[(c + 3) * FA_STR + li] = v.w;
            }
            const float* vrow = krow + DMODEL;   // v block = +512 columns
            #pragma unroll
            for (int u = 0; u < 4; ++u) {
                float4 v = *(const float4*)(vrow + u * 4);
                *(float4*)&Vs[li * FA_STR + lc + u * 4] = v;
            }
        }
        __syncthreads();

        // S = (Q*scale) K^T  -- 4x4 micro-tile per thread
        float s[4][4];
        #pragma unroll
        for (int i = 0; i < 4; ++i)
            #pragma unroll
            for (int j = 0; j < 4; ++j) s[i][j] = 0.f;

        #pragma unroll 8
        for (int d = 0; d < 64; ++d) {
            float4 aq = *(const float4*)&QsT[d * FA_STR + ty * 4];
            float4 bk = *(const float4*)&KsT[d * FA_STR + tx * 4];
            float ar[4] = {aq.x, aq.y, aq.z, aq.w};
            float br[4] = {bk.x, bk.y, bk.z, bk.w};
            #pragma unroll
            for (int i = 0; i < 4; ++i)
                #pragma unroll
                for (int j = 0; j < 4; ++j)
                    s[i][j] += ar[i] * br[j];
        }

        // Online softmax per row (16-lane butterfly across tx)
        #pragma unroll
        for (int i = 0; i < 4; ++i) {
            float mt = s[i][0];
            mt = fmaxf(mt, s[i][1]);
            mt = fmaxf(mt, s[i][2]);
            mt = fmaxf(mt, s[i][3]);
            mt = fmaxf(mt, __shfl_xor_sync(0xffffffffu, mt, 1));
            mt = fmaxf(mt, __shfl_xor_sync(0xffffffffu, mt, 2));
            mt = fmaxf(mt, __shfl_xor_sync(0xffffffffu, mt, 4));
            mt = fmaxf(mt, __shfl_xor_sync(0xffffffffu, mt, 8));

            const float mn   = fmaxf(m[i], mt);
            const float corr = __expf(m[i] - mn);
            m[i] = mn;

            float ps = 0.f;
            #pragma unroll
            for (int j = 0; j < 4; ++j) {
                s[i][j] = __expf(s[i][j] - mn);
                ps += s[i][j];
            }
            ps += __shfl_xor_sync(0xffffffffu, ps, 1);
            ps += __shfl_xor_sync(0xffffffffu, ps, 2);
            ps += __shfl_xor_sync(0xffffffffu, ps, 4);
            ps += __shfl_xor_sync(0xffffffffu, ps, 8);

            l[i] = l[i] * corr + ps;
            #pragma unroll
            for (int j = 0; j < 4; ++j) o[i][j] *= corr;

            *(float4*)&Ps[(ty * 4 + i) * FA_STR + tx * 4] =
                make_float4(s[i][0], s[i][1], s[i][2], s[i][3]);
        }
        __syncthreads();

        // O += P @ V
        #pragma unroll 4
        for (int j = 0; j < 64; ++j) {
            float4 vv = *(const float4*)&Vs[j * FA_STR + tx * 4];
            #pragma unroll
            for (int i = 0; i < 4; ++i) {
                const float pv = Ps[(ty * 4 + i) * FA_STR + j];
                o[i][0] += pv * vv.x;
                o[i][1] += pv * vv.y;
                o[i][2] += pv * vv.z;
                o[i][3] += pv * vv.w;
            }
        }
    }

    // Normalize and write out to g_attn[row][h*64 + d]
    #pragma unroll
    for (int i = 0; i < 4; ++i) {
        const float inv = 1.0f / l[i];
        const size_t row = (size_t)(bt * NTOK + rb * 64 + ty * 4 + i);
        float4 v = make_float4(o[i][0] * inv, o[i][1] * inv,
                               o[i][2] * inv, o[i][3] * inv);
        *(float4*)&g_attn[row * DMODEL + h * HD + tx * 4] = v;
    }
}

// ---------------------------------------------------------------------------
extern "C" void kernel_launch(void* const* d_in, const int* in_sizes, int n_in,
                              void* d_out, int out_size)
{
    const float* x      = (const float*)d_in[0];
    const float* W_qkv  = (const float*)d_in[1];
    const float* b_qkv  = (const float*)d_in[2];
    const float* W_proj = (const float*)d_in[3];
    const float* b_proj = (const float*)d_in[4];
    float* out = (float*)d_out;

    void* pqkv  = nullptr;
    void* pattn = nullptr;
    cudaGetSymbolAddress(&pqkv, g_qkv);
    cudaGetSymbolAddress(&pattn, g_attn);

    // K1: qkv = x @ W_qkv + b_qkv   (16384 x 1536 x 512)
    {
        dim3 grid(QKV_COLS / 128, MROWS / 128);
        sgemm_bias<<<grid, 256>>>(x, W_qkv, b_qkv, (float*)pqkv,
                                  MROWS, QKV_COLS, DMODEL);
    }

    // K2: flash attention
    {
        cudaFuncSetAttribute(flash_attn_kernel,
                             cudaFuncAttributeMaxDynamicSharedMemorySize,
                             FA_SMEM_BYTES);
        dim3 grid(NTOK / 64, BT_TOTAL * NHEADS);
        flash_attn_kernel<<<grid, 256, FA_SMEM_BYTES>>>();
    }

    // K3: out = attn @ W_proj + b_proj   (16384 x 512 x 512)
    {
        dim3 grid(DMODEL / 128, MROWS / 128);
        sgemm_bias<<<grid, 256>>>((const float*)pattn, W_proj, b_proj, out,
                                  MROWS, DMODEL, DMODEL);
    }
}

// round 3
// speedup vs baseline: 2.4389x; 2.4389x over previous
#include <cuda_runtime.h>
#include <cuda_bf16.h>
#include <cstdint>

// ---------------------------------------------------------------------------
// SpatialAttention on GB300 (sm_103, baseline PTX => HMMA tensor cores)
//   K0a: x -> bf16 hi/lo split
//   K0b: W_qkv^T, W_proj^T -> bf16 hi/lo (n-major, k-contiguous)
//   K1 : g_qkv = x @ W_qkv + b_qkv      (mma.sync split-bf16, fp32 out)
//   K2 : flash attention, mma.sync for QK^T and PV, frag-register softmax
//   K3 : out = attn @ W_proj + b_proj   (mma.sync split-bf16)
// ---------------------------------------------------------------------------

#define BT_TOTAL 16
#define NTOK     1024
#define DMODEL   512
#define NHEADS   8
#define HD       64
#define MROWS    (BT_TOTAL * NTOK)      // 16384
#define QKV_COLS (3 * DMODEL)           // 1536
#define KDIM     512

__device__ float          g_qkv[(size_t)MROWS * QKV_COLS];
__device__ __nv_bfloat16  g_x_hi[(size_t)MROWS * DMODEL];
__device__ __nv_bfloat16  g_x_lo[(size_t)MROWS * DMODEL];
__device__ __nv_bfloat16  g_wqt_hi[(size_t)QKV_COLS * DMODEL];
__device__ __nv_bfloat16  g_wqt_lo[(size_t)QKV_COLS * DMODEL];
__device__ __nv_bfloat16  g_wpt_hi[(size_t)DMODEL * DMODEL];
__device__ __nv_bfloat16  g_wpt_lo[(size_t)DMODEL * DMODEL];
__device__ __nv_bfloat16  g_attn_hi[(size_t)MROWS * DMODEL];
__device__ __nv_bfloat16  g_attn_lo[(size_t)MROWS * DMODEL];

// ---------------------------------------------------------------------------
// helpers
// ---------------------------------------------------------------------------
__device__ __forceinline__ uint32_t smem_u32(const void* p) {
    uint32_t a;
    asm("{ .reg .u64 t; cvta.to.shared.u64 t, %1; cvt.u32.u64 %0, t; }"
        : "=r"(a) : "l"(p));
    return a;
}

__device__ __forceinline__ void ldsm4(uint32_t* r, uint32_t a) {
    asm volatile("ldmatrix.sync.aligned.m8n8.x4.shared.b16 {%0,%1,%2,%3}, [%4];"
        : "=r"(r[0]), "=r"(r[1]), "=r"(r[2]), "=r"(r[3]) : "r"(a));
}
__device__ __forceinline__ void ldsm4t(uint32_t* r, uint32_t a) {
    asm volatile("ldmatrix.sync.aligned.m8n8.x4.trans.shared.b16 {%0,%1,%2,%3}, [%4];"
        : "=r"(r[0]), "=r"(r[1]), "=r"(r[2]), "=r"(r[3]) : "r"(a));
}
__device__ __forceinline__ void mma16816(float* d, const uint32_t* a, const uint32_t* b) {
    asm volatile("mma.sync.aligned.m16n8k16.row.col.f32.bf16.bf16.f32 "
        "{%0,%1,%2,%3},{%4,%5,%6,%7},{%8,%9},{%0,%1,%2,%3};"
        : "+f"(d[0]), "+f"(d[1]), "+f"(d[2]), "+f"(d[3])
        : "r"(a[0]), "r"(a[1]), "r"(a[2]), "r"(a[3]), "r"(b[0]), "r"(b[1]));
}
__device__ __forceinline__ void cp_async16(uint32_t s, const void* g) {
    asm volatile("cp.async.cg.shared.global [%0], [%1], 16;" :: "r"(s), "l"(g));
}
#define CP_COMMIT() asm volatile("cp.async.commit_group;")
#define CP_WAIT(n)  asm volatile("cp.async.wait_group %0;" :: "n"(n) : "memory")

// pack 2 floats -> bf16x2 hi + bf16x2 lo residual
__device__ __forceinline__ void hilo2(float a, float b, uint32_t& h, uint32_t& l) {
    __nv_bfloat162 hb = __floats2bfloat162_rn(a, b);
    float2 hf = __bfloat1622float2(hb);
    __nv_bfloat162 lb = __floats2bfloat162_rn(a - hf.x, b - hf.y);
    h = *(uint32_t*)&hb;
    l = *(uint32_t*)&lb;
}

// ---------------------------------------------------------------------------
// K0a: fp32 -> bf16 hi/lo split
// ---------------------------------------------------------------------------
__global__ void cvt_hilo(const float* __restrict__ X, __nv_bfloat16* __restrict__ H,
                         __nv_bfloat16* __restrict__ L, int n4)
{
    int i = blockIdx.x * blockDim.x + threadIdx.x;
    if (i >= n4) return;
    float4 v = ((const float4*)X)[i];
    uint32_t h0, l0, h1, l1;
    hilo2(v.x, v.y, h0, l0);
    hilo2(v.z, v.w, h1, l1);
    ((uint32_t*)H)[i * 2 + 0] = h0;
    ((uint32_t*)H)[i * 2 + 1] = h1;
    ((uint32_t*)L)[i * 2 + 0] = l0;
    ((uint32_t*)L)[i * 2 + 1] = l1;
}

// ---------------------------------------------------------------------------
// K0b: transpose + split: T[n][k] = W[k][n]
// ---------------------------------------------------------------------------
__global__ void transpose_cvt(const float* __restrict__ W, __nv_bfloat16* __restrict__ Th,
                              __nv_bfloat16* __restrict__ Tl, int K, int N)
{
    __shared__ float tile[32][33];
    const int bx = blockIdx.x * 32;   // n
    const int by = blockIdx.y * 32;   // k
    const int tx = threadIdx.x, ty = threadIdx.y;   // 32 x 8
    #pragma unroll
    for (int i = 0; i < 32; i += 8)
        tile[ty + i][tx] = W[(size_t)(by + ty + i) * N + bx + tx];
    __syncthreads();
    #pragma unroll
    for (int i = 0; i < 32; i += 8) {
        float v = tile[tx][ty + i];
        size_t o = (size_t)(bx + ty + i) * K + by + tx;
        __nv_bfloat16 h = __float2bfloat16(v);
        Th[o] = h;
        Tl[o] = __float2bfloat16(v - __bfloat162float(h));
    }
}

// ---------------------------------------------------------------------------
// mma.sync split-bf16 GEMM: C[M,Ntot] = (Ah+Al)[M,512] @ (Bh+Bl)[Ntot,512]^T + bias
// CTA tile 128x128, warps 2x4 (warp tile 64x32), k-chunk 32, cp.async dbl-buf.
// SMEM rows padded to 80B: bank-group (5r+b) mod 8 is a permutation => LDSM
// conflict-free.
// ---------------------------------------------------------------------------
#define GCH   32
#define GROWB 80
#define GBUF  (128 * GROWB)         // 10240
#define GEMM_SMEM (8 * GBUF)        // 81920

__global__ __launch_bounds__(256, 2)
void gemm_mma(const __nv_bfloat16* __restrict__ Ah, const __nv_bfloat16* __restrict__ Al,
              const __nv_bfloat16* __restrict__ Bh, const __nv_bfloat16* __restrict__ Bl,
              const float* __restrict__ bias, float* __restrict__ C, int Ntot)
{
    extern __shared__ char sm[];
    const uint32_t sb = smem_u32(sm);
    const int t = threadIdx.x, lane = t & 31, w = t >> 5;
    const int wm = w >> 2, wn = w & 3;
    const int bm = blockIdx.y * 128, bn = blockIdx.x * 128;

    // loader mapping: each thread owns (row, 32B block-pair) per matrix
    const int lrow = t & 127;
    const int lbp  = t >> 7;                 // 0/1
    const __nv_bfloat16* pA  = Ah + (size_t)(bm + lrow) * KDIM + lbp * 16;
    const __nv_bfloat16* pAl = Al + (size_t)(bm + lrow) * KDIM + lbp * 16;
    const __nv_bfloat16* pB  = Bh + (size_t)(bn + lrow) * KDIM + lbp * 16;
    const __nv_bfloat16* pBl = Bl + (size_t)(bn + lrow) * KDIM + lbp * 16;
    const uint32_t sdst = (uint32_t)(lrow * GROWB + lbp * 32);

    float acc[4][4][4];
    #pragma unroll
    for (int a = 0; a < 4; ++a)
        #pragma unroll
        for (int b = 0; b < 4; ++b)
            #pragma unroll
            for (int c = 0; c < 4; ++c) acc[a][b][c] = 0.f;

    // prefetch chunk 0 into stage 0
    {
        uint32_t s0 = sb + sdst;
        cp_async16(s0 + 0 * GBUF,      pA);
        cp_async16(s0 + 0 * GBUF + 16, pA + 8);
        cp_async16(s0 + 1 * GBUF,      pAl);
        cp_async16(s0 + 1 * GBUF + 16, pAl + 8);
        cp_async16(s0 + 2 * GBUF,      pB);
        cp_async16(s0 + 2 * GBUF + 16, pB + 8);
        cp_async16(s0 + 3 * GBUF,      pBl);
        cp_async16(s0 + 3 * GBUF + 16, pBl + 8);
        CP_COMMIT();
    }

    for (int c = 0; c < 16; ++c) {
        if (c + 1 < 16) {
            const int koff = (c + 1) * GCH;
            uint32_t s1 = sb + ((c + 1) & 1) * 4 * GBUF + sdst;
            cp_async16(s1 + 0 * GBUF,      pA  + koff);
            cp_async16(s1 + 0 * GBUF + 16, pA  + koff + 8);
            cp_async16(s1 + 1 * GBUF,      pAl + koff);
            cp_async16(s1 + 1 * GBUF + 16, pAl + koff + 8);
            cp_async16(s1 + 2 * GBUF,      pB  + koff);
            cp_async16(s1 + 2 * GBUF + 16, pB  + koff + 8);
            cp_async16(s1 + 3 * GBUF,      pBl + koff);
            cp_async16(s1 + 3 * GBUF + 16, pBl + koff + 8);
            CP_COMMIT();
            CP_WAIT(1);
        } else {
            CP_WAIT(0);
        }
        __syncthreads();

        const uint32_t aH = sb + ((c & 1) * 4 + 0) * GBUF;
        const uint32_t aL = sb + ((c & 1) * 4 + 1) * GBUF;
        const uint32_t bH = sb + ((c & 1) * 4 + 2) * GBUF;
        const uint32_t bL = sb + ((c & 1) * 4 + 3) * GBUF;

        #pragma unroll
        for (int ks = 0; ks < 2; ++ks) {
            uint32_t bh[2][4], bl[2][4];
            #pragma unroll
            for (int j = 0; j < 2; ++j) {
                const uint32_t n   = wn * 32 + j * 16 + (lane >> 4) * 8 + (lane & 7);
                const uint32_t blk = 2 * ks + ((lane >> 3) & 1);
                ldsm4(bh[j], bH + n * GROWB + blk * 16);
                ldsm4(bl[j], bL + n * GROWB + blk * 16);
            }
            #pragma unroll
            for (int mf = 0; mf < 4; ++mf) {
                uint32_t ah[4], al[4];
                const uint32_t r   = wm * 64 + mf * 16 + ((lane >> 3) & 1) * 8 + (lane & 7);
                const uint32_t blk = 2 * ks + (lane >> 4);
                ldsm4(ah, aH + r * GROWB + blk * 16);
                ldsm4(al, aL + r * GROWB + blk * 16);
                #pragma unroll
                for (int nf = 0; nf < 4; ++nf) {
                    const uint32_t* bhp = &bh[nf >> 1][(nf & 1) * 2];
                    const uint32_t* blp = &bl[nf >> 1][(nf & 1) * 2];
                    mma16816(acc[mf][nf], ah, bhp);
                    mma16816(acc[mf][nf], ah, blp);
                    mma16816(acc[mf][nf], al, bhp);
                }
            }
        }
        __syncthreads();
    }

    // epilogue
    const int g = lane >> 2, q2 = (lane & 3) * 2;
    #pragma unroll
    for (int mf = 0; mf < 4; ++mf) {
        const int r0 = bm + wm * 64 + mf * 16 + g;
        #pragma unroll
        for (int nf = 0; nf < 4; ++nf) {
            const int col = bn + wn * 32 + nf * 8 + q2;
            const float b0 = bias[col], b1 = bias[col + 1];
            float2 v0 = make_float2(acc[mf][nf][0] + b0, acc[mf][nf][1] + b1);
            float2 v1 = make_float2(acc[mf][nf][2] + b0, acc[mf][nf][3] + b1);
            *(float2*)&C[(size_t)r0 * Ntot + col]       = v0;
            *(float2*)&C[(size_t)(r0 + 8) * Ntot + col] = v1;
        }
    }
}

// ---------------------------------------------------------------------------
// Flash attention with mma.sync (split bf16, fp32 accum, FA2 frag softmax).
// CTA: 128 q rows x (bt,h) pair; 8 warps, 16 q rows each; key tiles of 64.
// SMEM: Qh,Ql [128][64] bf16 (16KB ea), Kh,Kl,Vh,Vl [64][64] (8KB ea) = 64KB.
// 128B rows, XOR-8 swizzle (16B block index ^= row&7) => LDSM conflict-free.
// ---------------------------------------------------------------------------
#define FQ_H 0
#define FQ_L 16384
#define FK_H 32768
#define FK_L 40960
#define FV_H 49152
#define FV_L 57344
#define FLASH_SMEM 65536

__global__ __launch_bounds__(256, 2)
void flash_mma()
{
    const int rb = blockIdx.x;          // 0..7 (128-row q block)
    const int pp = blockIdx.y;          // bt*8 + h
    const int bt = pp >> 3, h = pp & 7;
    extern __shared__ char sm[];
    const uint32_t sb = smem_u32(sm);
    const int t = threadIdx.x, lane = t & 31, w = t >> 5;
    const size_t base = (size_t)bt * NTOK * QKV_COLS;

    // ---- load Q (scaled by 1/8, split hi/lo) ----
    {
        const int row = t >> 1, half = t & 1;
        const float* src = g_qkv + base + (size_t)(rb * 128 + row) * QKV_COLS
                         + h * HD + half * 32;
        #pragma unroll
        for (int i = 0; i < 4; ++i) {
            float4 v0 = *(const float4*)(src + i * 8);
            float4 v1 = *(const float4*)(src + i * 8 + 4);
            uint32_t h0, l0, h1, l1, h2, l2, h3, l3;
            hilo2(v0.x * 0.125f, v0.y * 0.125f, h0, l0);
            hilo2(v0.z * 0.125f, v0.w * 0.125f, h1, l1);
            hilo2(v1.x * 0.125f, v1.y * 0.125f, h2, l2);
            hilo2(v1.z * 0.125f, v1.w * 0.125f, h3, l3);
            const int blk = half * 4 + i;
            const uint32_t off = row * 128 + ((blk ^ (row & 7)) * 16);
            *(uint4*)(sm + FQ_H + off) = make_uint4(h0, h1, h2, h3);
            *(uint4*)(sm + FQ_L + off) = make_uint4(l0, l1, l2, l3);
        }
    }

    float s_m0 = -1e30f, s_m1 = -1e30f, s_l0 = 0.f, s_l1 = 0.f;
    float o[8][4];
    #pragma unroll
    for (int nf = 0; nf < 8; ++nf)
        #pragma unroll
        for (int i = 0; i < 4; ++i) o[nf][i] = 0.f;

    const int g = lane >> 2, q2 = (lane & 3) * 2;

    for (int kb = 0; kb < 16; ++kb) {
        __syncthreads();   // prior tile consumed (also orders Q stores, iter 0)
        // ---- load K,V tile (64 rows), split hi/lo ----
        {
            const int r = t >> 2, qd = t & 3;
            const float* ksrc = g_qkv + base + (size_t)(kb * 64 + r) * QKV_COLS
                              + DMODEL + h * HD + qd * 16;
            const float* vsrc = ksrc + DMODEL;
            #pragma unroll
            for (int i = 0; i < 2; ++i) {
                const int blk = qd * 2 + i;
                const uint32_t off = r * 128 + ((blk ^ (r & 7)) * 16);
                float4 a0 = *(const float4*)(ksrc + i * 8);
                float4 a1 = *(const float4*)(ksrc + i * 8 + 4);
                uint32_t h0, l0, h1, l1, h2, l2, h3, l3;
                hilo2(a0.x, a0.y, h0, l0);
                hilo2(a0.z, a0.w, h1, l1);
                hilo2(a1.x, a1.y, h2, l2);
                hilo2(a1.z, a1.w, h3, l3);
                *(uint4*)(sm + FK_H + off) = make_uint4(h0, h1, h2, h3);
                *(uint4*)(sm + FK_L + off) = make_uint4(l0, l1, l2, l3);
                float4 b0 = *(const float4*)(vsrc + i * 8);
                float4 b1 = *(const float4*)(vsrc + i * 8 + 4);
                hilo2(b0.x, b0.y, h0, l0);
                hilo2(b0.z, b0.w, h1, l1);
                hilo2(b1.x, b1.y, h2, l2);
                hilo2(b1.z, b1.w, h3, l3);
                *(uint4*)(sm + FV_H + off) = make_uint4(h0, h1, h2, h3);
                *(uint4*)(sm + FV_L + off) = make_uint4(l0, l1, l2, l3);
            }
        }
        __syncthreads();

        // ---- S = (Q/8) @ K^T : 16 rows x 64 keys per warp ----
        float s[8][4];
        #pragma unroll
        for (int nf = 0; nf < 8; ++nf)
            #pragma unroll
            for (int i = 0; i < 4; ++i) s[nf][i] = 0.f;

        #pragma unroll
        for (int ks = 0; ks < 4; ++ks) {
            uint32_t ah[4], al[4];
            {
                const uint32_t r   = w * 16 + ((lane >> 3) & 1) * 8 + (lane & 7);
                const uint32_t blk = 2 * ks + (lane >> 4);
                const uint32_t off = r * 128 + ((blk ^ (r & 7)) * 16);
                ldsm4(ah, sb + FQ_H + off);
                ldsm4(al, sb + FQ_L + off);
            }
            #pragma unroll
            for (int j = 0; j < 4; ++j) {
                uint32_t bh[4], bl[4];
                const uint32_t key = j * 16 + (lane >> 4) * 8 + (lane & 7);
                const uint32_t blk = 2 * ks + ((lane >> 3) & 1);
                const uint32_t off = key * 128 + ((blk ^ (key & 7)) * 16);
                ldsm4(bh, sb + FK_H + off);
                ldsm4(bl, sb + FK_L + off);
                mma16816(s[2 * j],     ah, &bh[0]);
                mma16816(s[2 * j],     ah, &bl[0]);
                mma16816(s[2 * j],     al, &bh[0]);
                mma16816(s[2 * j + 1], ah, &bh[2]);
                mma16816(s[2 * j + 1], ah, &bl[2]);
                mma16816(s[2 * j + 1], al, &bh[2]);
            }
        }

        // ---- online softmax on fragments (rows g and g+8) ----
        float mt0 = -1e30f, mt1 = -1e30f;
        #pragma unroll
        for (int nf = 0; nf < 8; ++nf) {
            mt0 = fmaxf(mt0, fmaxf(s[nf][0], s[nf][1]));
            mt1 = fmaxf(mt1, fmaxf(s[nf][2], s[nf][3]));
        }
        mt0 = fmaxf(mt0, __shfl_xor_sync(0xffffffffu, mt0, 1));
        mt0 = fmaxf(mt0, __shfl_xor_sync(0xffffffffu, mt0, 2));
        mt1 = fmaxf(mt1, __shfl_xor_sync(0xffffffffu, mt1, 1));
        mt1 = fmaxf(mt1, __shfl_xor_sync(0xffffffffu, mt1, 2));

        const float mn0 = fmaxf(s_m0, mt0), mn1 = fmaxf(s_m1, mt1);
        const float c0 = __expf(s_m0 - mn0), c1 = __expf(s_m1 - mn1);
        s_m0 = mn0; s_m1 = mn1;

        float ps0 = 0.f, ps1 = 0.f;
        #pragma unroll
        for (int nf = 0; nf < 8; ++nf) {
            s[nf][0] = __expf(s[nf][0] - mn0);
            s[nf][1] = __expf(s[nf][1] - mn0);
            s[nf][2] = __expf(s[nf][2] - mn1);
            s[nf][3] = __expf(s[nf][3] - mn1);
            ps0 += s[nf][0] + s[nf][1];
            ps1 += s[nf][2] + s[nf][3];
        }
        ps0 += __shfl_xor_sync(0xffffffffu, ps0, 1);
        ps0 += __shfl_xor_sync(0xffffffffu, ps0, 2);
        ps1 += __shfl_xor_sync(0xffffffffu, ps1, 1);
        ps1 += __shfl_xor_sync(0xffffffffu, ps1, 2);
        s_l0 = s_l0 * c0 + ps0;
        s_l1 = s_l1 * c1 + ps1;

        #pragma unroll
        for (int nf = 0; nf < 8; ++nf) {
            o[nf][0] *= c0; o[nf][1] *= c0;
            o[nf][2] *= c1; o[nf][3] *= c1;
        }

        // ---- O += P @ V : P repacked in registers to A-frags (hi/lo) ----
        #pragma unroll
        for (int ks = 0; ks < 4; ++ks) {
            uint32_t ph[4], pl[4];
            hilo2(s[2 * ks][0],     s[2 * ks][1],     ph[0], pl[0]);
            hilo2(s[2 * ks][2],     s[2 * ks][3],     ph[1], pl[1]);
            hilo2(s[2 * ks + 1][0], s[2 * ks + 1][1], ph[2], pl[2]);
            hilo2(s[2 * ks + 1][2], s[2 * ks + 1][3], ph[3], pl[3]);
            #pragma unroll
            for (int j = 0; j < 4; ++j) {
                uint32_t vh[4], vl[4];
                const uint32_t key = ks * 16 + ((lane >> 3) & 1) * 8 + (lane & 7);
                const uint32_t blk = 2 * j + (lane >> 4);
                const uint32_t off = key * 128 + ((blk ^ (key & 7)) * 16);
                ldsm4t(vh, sb + FV_H + off);
                ldsm4t(vl, sb + FV_L + off);
                mma16816(o[2 * j],     ph, &vh[0]);
                mma16816(o[2 * j],     ph, &vl[0]);
                mma16816(o[2 * j],     pl, &vh[0]);
                mma16816(o[2 * j + 1], ph, &vh[2]);
                mma16816(o[2 * j + 1], ph, &vl[2]);
                mma16816(o[2 * j + 1], pl, &vh[2]);
            }
        }
    }

    // ---- epilogue: normalize, split hi/lo, store ----
    const float inv0 = 1.0f / s_l0, inv1 = 1.0f / s_l1;
    const size_t row0 = (size_t)bt * NTOK + rb * 128 + w * 16 + g;
    const size_t row1 = row0 + 8;
    #pragma unroll
    for (int nf = 0; nf < 8; ++nf) {
        const int col = h * HD + nf * 8 + q2;
        uint32_t hh, ll;
        hilo2(o[nf][0] * inv0, o[nf][1] * inv0, hh, ll);
        *(uint32_t*)&g_attn_hi[row0 * DMODEL + col] = hh;
        *(uint32_t*)&g_attn_lo[row0 * DMODEL + col] = ll;
        hilo2(o[nf][2] * inv1, o[nf][3] * inv1, hh, ll);
        *(uint32_t*)&g_attn_hi[row1 * DMODEL + col] = hh;
        *(uint32_t*)&g_attn_lo[row1 * DMODEL + col] = ll;
    }
}

// ---------------------------------------------------------------------------
extern "C" void kernel_launch(void* const* d_in, const int* in_sizes, int n_in,
                              void* d_out, int out_size)
{
    const float* x      = (const float*)d_in[0];
    const float* W_qkv  = (const float*)d_in[1];
    const float* b_qkv  = (const float*)d_in[2];
    const float* W_proj = (const float*)d_in[3];
    const float* b_proj = (const float*)d_in[4];
    float* out = (float*)d_out;

    void *pqkv, *pxh, *pxl, *pwqh, *pwql, *pwph, *pwpl, *pah, *pal;
    cudaGetSymbolAddress(&pqkv, g_qkv);
    cudaGetSymbolAddress(&pxh, g_x_hi);    cudaGetSymbolAddress(&pxl, g_x_lo);
    cudaGetSymbolAddress(&pwqh, g_wqt_hi); cudaGetSymbolAddress(&pwql, g_wqt_lo);
    cudaGetSymbolAddress(&pwph, g_wpt_hi); cudaGetSymbolAddress(&pwpl, g_wpt_lo);
    cudaGetSymbolAddress(&pah, g_attn_hi); cudaGetSymbolAddress(&pal, g_attn_lo);

    cudaFuncSetAttribute(gemm_mma,
                         cudaFuncAttributeMaxDynamicSharedMemorySize, GEMM_SMEM);
    cudaFuncSetAttribute(flash_mma,
                         cudaFuncAttributeMaxDynamicSharedMemorySize, FLASH_SMEM);

    // K0a: split x
    {
        const int n4 = MROWS * DMODEL / 4;
        cvt_hilo<<<(n4 + 255) / 256, 256>>>(x, (__nv_bfloat16*)pxh,
                                            (__nv_bfloat16*)pxl, n4);
    }
    // K0b: transpose + split weights
    {
        dim3 blk(32, 8);
        transpose_cvt<<<dim3(QKV_COLS / 32, DMODEL / 32), blk>>>(
            W_qkv, (__nv_bfloat16*)pwqh, (__nv_bfloat16*)pwql, DMODEL, QKV_COLS);
        transpose_cvt<<<dim3(DMODEL / 32, DMODEL / 32), blk>>>(
            W_proj, (__nv_bfloat16*)pwph, (__nv_bfloat16*)pwpl, DMODEL, DMODEL);
    }
    // K1: qkv projection
    {
        dim3 grid(QKV_COLS / 128, MROWS / 128);
        gemm_mma<<<grid, 256, GEMM_SMEM>>>(
            (const __nv_bfloat16*)pxh, (const __nv_bfloat16*)pxl,
            (const __nv_bfloat16*)pwqh, (const __nv_bfloat16*)pwql,
            b_qkv, (float*)pqkv, QKV_COLS);
    }
    // K2: flash attention
    {
        dim3 grid(NTOK / 128, BT_TOTAL * NHEADS);
        flash_mma<<<grid, 256, FLASH_SMEM>>>();
    }
    // K3: output projection
    {
        dim3 grid(DMODEL / 128, MROWS / 128);
        gemm_mma<<<grid, 256, GEMM_SMEM>>>(
            (const __nv_bfloat16*)pah, (const __nv_bfloat16*)pal,
            (const __nv_bfloat16*)pwph, (const __nv_bfloat16*)pwpl,
            b_proj, out, DMODEL);
    }
}

// round 4
// speedup vs baseline: 3.0346x; 1.2442x over previous
#include <cuda_runtime.h>
#include <cuda_bf16.h>
#include <cstdint>

// ---------------------------------------------------------------------------
// SpatialAttention on GB300 (sm_103, mma.sync HMMA path)
//   K0a: x -> bf16 hi/lo split
//   K0b: W_qkv^T, W_proj^T -> bf16 hi/lo
//   K1 : qkv_hi/lo = x @ W_qkv + b_qkv   (split-bf16 mma GEMM, bf16 hi/lo out)
//   K2 : flash attention (cp.async bf16 tiles, frag softmax, hi/lo out)
//   K3 : out = attn @ W_proj + b_proj    (split-bf16 mma GEMM, fp32 out)
// ---------------------------------------------------------------------------

#define BT_TOTAL 16
#define NTOK     1024
#define DMODEL   512
#define NHEADS   8
#define HD       64
#define MROWS    (BT_TOTAL * NTOK)      // 16384
#define QKV_COLS (3 * DMODEL)           // 1536
#define KDIM     512

__device__ __nv_bfloat16  g_qkvh[(size_t)MROWS * QKV_COLS];
__device__ __nv_bfloat16  g_qkvl[(size_t)MROWS * QKV_COLS];
__device__ __nv_bfloat16  g_x_hi[(size_t)MROWS * DMODEL];
__device__ __nv_bfloat16  g_x_lo[(size_t)MROWS * DMODEL];
__device__ __nv_bfloat16  g_wqt_hi[(size_t)QKV_COLS * DMODEL];
__device__ __nv_bfloat16  g_wqt_lo[(size_t)QKV_COLS * DMODEL];
__device__ __nv_bfloat16  g_wpt_hi[(size_t)DMODEL * DMODEL];
__device__ __nv_bfloat16  g_wpt_lo[(size_t)DMODEL * DMODEL];
__device__ __nv_bfloat16  g_attn_hi[(size_t)MROWS * DMODEL];
__device__ __nv_bfloat16  g_attn_lo[(size_t)MROWS * DMODEL];

// ---------------------------------------------------------------------------
// helpers
// ---------------------------------------------------------------------------
__device__ __forceinline__ uint32_t smem_u32(const void* p) {
    uint32_t a;
    asm("{ .reg .u64 t; cvta.to.shared.u64 t, %1; cvt.u32.u64 %0, t; }"
        : "=r"(a) : "l"(p));
    return a;
}
__device__ __forceinline__ void ldsm4(uint32_t* r, uint32_t a) {
    asm volatile("ldmatrix.sync.aligned.m8n8.x4.shared.b16 {%0,%1,%2,%3}, [%4];"
        : "=r"(r[0]), "=r"(r[1]), "=r"(r[2]), "=r"(r[3]) : "r"(a));
}
__device__ __forceinline__ void ldsm4t(uint32_t* r, uint32_t a) {
    asm volatile("ldmatrix.sync.aligned.m8n8.x4.trans.shared.b16 {%0,%1,%2,%3}, [%4];"
        : "=r"(r[0]), "=r"(r[1]), "=r"(r[2]), "=r"(r[3]) : "r"(a));
}
__device__ __forceinline__ void mma16816(float* d, const uint32_t* a, const uint32_t* b) {
    asm volatile("mma.sync.aligned.m16n8k16.row.col.f32.bf16.bf16.f32 "
        "{%0,%1,%2,%3},{%4,%5,%6,%7},{%8,%9},{%0,%1,%2,%3};"
        : "+f"(d[0]), "+f"(d[1]), "+f"(d[2]), "+f"(d[3])
        : "r"(a[0]), "r"(a[1]), "r"(a[2]), "r"(a[3]), "r"(b[0]), "r"(b[1]));
}
__device__ __forceinline__ void cp_async16(uint32_t s, const void* g) {
    asm volatile("cp.async.cg.shared.global [%0], [%1], 16;" :: "r"(s), "l"(g));
}
#define CP_COMMIT() asm volatile("cp.async.commit_group;")
#define CP_WAIT(n)  asm volatile("cp.async.wait_group %0;" :: "n"(n) : "memory")

__device__ __forceinline__ void hilo2(float a, float b, uint32_t& h, uint32_t& l) {
    __nv_bfloat162 hb = __floats2bfloat162_rn(a, b);
    float2 hf = __bfloat1622float2(hb);
    __nv_bfloat162 lb = __floats2bfloat162_rn(a - hf.x, b - hf.y);
    h = *(uint32_t*)&hb;
    l = *(uint32_t*)&lb;
}

// ---------------------------------------------------------------------------
// K0a / K0b prep
// ---------------------------------------------------------------------------
__global__ void cvt_hilo(const float* __restrict__ X, __nv_bfloat16* __restrict__ H,
                         __nv_bfloat16* __restrict__ L, int n4)
{
    int i = blockIdx.x * blockDim.x + threadIdx.x;
    if (i >= n4) return;
    float4 v = ((const float4*)X)[i];
    uint32_t h0, l0, h1, l1;
    hilo2(v.x, v.y, h0, l0);
    hilo2(v.z, v.w, h1, l1);
    ((uint32_t*)H)[i * 2 + 0] = h0;
    ((uint32_t*)H)[i * 2 + 1] = h1;
    ((uint32_t*)L)[i * 2 + 0] = l0;
    ((uint32_t*)L)[i * 2 + 1] = l1;
}

__global__ void transpose_cvt(const float* __restrict__ W, __nv_bfloat16* __restrict__ Th,
                              __nv_bfloat16* __restrict__ Tl, int K, int N)
{
    __shared__ float tile[32][33];
    const int bx = blockIdx.x * 32;
    const int by = blockIdx.y * 32;
    const int tx = threadIdx.x, ty = threadIdx.y;
    #pragma unroll
    for (int i = 0; i < 32; i += 8)
        tile[ty + i][tx] = W[(size_t)(by + ty + i) * N + bx + tx];
    __syncthreads();
    #pragma unroll
    for (int i = 0; i < 32; i += 8) {
        float v = tile[tx][ty + i];
        size_t o = (size_t)(bx + ty + i) * K + by + tx;
        __nv_bfloat16 h = __float2bfloat16(v);
        Th[o] = h;
        Tl[o] = __float2bfloat16(v - __bfloat162float(h));
    }
}

// ---------------------------------------------------------------------------
// split-bf16 GEMM: CTA tile 128x256, 512 threads (16 warps, warp tile 64x32),
// k-chunk 32, 3-stage cp.async pipeline, one __syncthreads per chunk.
// SMEM rows padded to 80B -> (5r+b) mod 8 permutation, LDSM conflict-free.
// Output: fp32 (Cf) or bf16 hi/lo (Chi/Clo) when Chi != nullptr.
// ---------------------------------------------------------------------------
#define GROWB 80
#define G_A   (128 * GROWB)             // 10240
#define G_B   (256 * GROWB)             // 20480
#define GSTG  (2 * G_A + 2 * G_B)       // 61440: Ah, Al, Bh, Bl
#define GEMM_SMEM (3 * GSTG)            // 184320

__global__ __launch_bounds__(512, 1)
void gemm_mma(const __nv_bfloat16* __restrict__ Ah, const __nv_bfloat16* __restrict__ Al,
              const __nv_bfloat16* __restrict__ Bh, const __nv_bfloat16* __restrict__ Bl,
              const float* __restrict__ bias, float* __restrict__ Cf,
              __nv_bfloat16* __restrict__ Chi, __nv_bfloat16* __restrict__ Clo, int Ntot)
{
    extern __shared__ char sm[];
    const uint32_t sb = smem_u32(sm);
    const int t = threadIdx.x, lane = t & 31, w = t >> 5;
    const int wm = w >> 3, wn = w & 7;
    const int bm = blockIdx.y * 128, bn = blockIdx.x * 256;

    // loaders
    const int arow = t >> 2, ablk = t & 3;                 // 128 rows x 4 blks
    const __nv_bfloat16* pAh = Ah + (size_t)(bm + arow) * KDIM + ablk * 8;
    const __nv_bfloat16* pAl = Al + (size_t)(bm + arow) * KDIM + ablk * 8;
    const uint32_t adst = (uint32_t)(arow * GROWB + ablk * 16);
    const int brow0 = t >> 2, brow1 = (t + 512) >> 2;      // 256 rows x 4 blks
    const int bblk0 = t & 3,  bblk1 = (t + 512) & 3;
    const __nv_bfloat16* pBh0 = Bh + (size_t)(bn + brow0) * KDIM + bblk0 * 8;
    const __nv_bfloat16* pBh1 = Bh + (size_t)(bn + brow1) * KDIM + bblk1 * 8;
    const __nv_bfloat16* pBl0 = Bl + (size_t)(bn + brow0) * KDIM + bblk0 * 8;
    const __nv_bfloat16* pBl1 = Bl + (size_t)(bn + brow1) * KDIM + bblk1 * 8;
    const uint32_t bdst0 = (uint32_t)(brow0 * GROWB + bblk0 * 16);
    const uint32_t bdst1 = (uint32_t)(brow1 * GROWB + bblk1 * 16);

    float acc[4][4][4];
    #pragma unroll
    for (int a = 0; a < 4; ++a)
        #pragma unroll
        for (int b = 0; b < 4; ++b)
            #pragma unroll
            for (int c = 0; c < 4; ++c) acc[a][b][c] = 0.f;

    // prologue: chunks 0 and 1
    #pragma unroll
    for (int c = 0; c < 2; ++c) {
        const int koff = c * 32;
        const uint32_t st = sb + c * GSTG;
        cp_async16(st + adst,                pAh + koff);
        cp_async16(st + G_A + adst,          pAl + koff);
        cp_async16(st + 2 * G_A + bdst0,         pBh0 + koff);
        cp_async16(st + 2 * G_A + bdst1,         pBh1 + koff);
        cp_async16(st + 2 * G_A + G_B + bdst0,   pBl0 + koff);
        cp_async16(st + 2 * G_A + G_B + bdst1,   pBl1 + koff);
        CP_COMMIT();
    }

    int stg = 0;
    for (int c = 0; c < 16; ++c) {
        if (c < 14) CP_WAIT(1); else CP_WAIT(0);
        __syncthreads();

        if (c + 2 < 16) {
            const int koff = (c + 2) * 32;
            const int s2 = (stg + 2 == 3) ? 0 : ((stg + 2 == 4) ? 1 : stg + 2);
            const uint32_t st = sb + s2 * GSTG;
            cp_async16(st + adst,              pAh + koff);
            cp_async16(st + G_A + adst,        pAl + koff);
            cp_async16(st + 2 * G_A + bdst0,       pBh0 + koff);
            cp_async16(st + 2 * G_A + bdst1,       pBh1 + koff);
            cp_async16(st + 2 * G_A + G_B + bdst0, pBl0 + koff);
            cp_async16(st + 2 * G_A + G_B + bdst1, pBl1 + koff);
            CP_COMMIT();
        }

        const uint32_t aH = sb + stg * GSTG;
        const uint32_t aL = aH + G_A;
        const uint32_t bH = aH + 2 * G_A;
        const uint32_t bL = bH + G_B;

        #pragma unroll
        for (int ks = 0; ks < 2; ++ks) {
            uint32_t bh[2][4], bl[2][4];
            #pragma unroll
            for (int j = 0; j < 2; ++j) {
                const uint32_t n   = wn * 32 + j * 16 + (lane >> 4) * 8 + (lane & 7);
                const uint32_t blk = 2 * ks + ((lane >> 3) & 1);
                ldsm4(bh[j], bH + n * GROWB + blk * 16);
                ldsm4(bl[j], bL + n * GROWB + blk * 16);
            }
            #pragma unroll
            for (int mf = 0; mf < 4; ++mf) {
                uint32_t ah[4], al[4];
                const uint32_t r   = wm * 64 + mf * 16 + ((lane >> 3) & 1) * 8 + (lane & 7);
                const uint32_t blk = 2 * ks + (lane >> 4);
                ldsm4(ah, aH + r * GROWB + blk * 16);
                ldsm4(al, aL + r * GROWB + blk * 16);
                #pragma unroll
                for (int nf = 0; nf < 4; ++nf) {
                    const uint32_t* bhp = &bh[nf >> 1][(nf & 1) * 2];
                    const uint32_t* blp = &bl[nf >> 1][(nf & 1) * 2];
                    mma16816(acc[mf][nf], ah, bhp);
                    mma16816(acc[mf][nf], ah, blp);
                    mma16816(acc[mf][nf], al, bhp);
                }
            }
        }
        stg = (stg == 2) ? 0 : stg + 1;
    }

    // epilogue
    const int g = lane >> 2, q2 = (lane & 3) * 2;
    #pragma unroll
    for (int mf = 0; mf < 4; ++mf) {
        const int r0 = bm + wm * 64 + mf * 16 + g;
        #pragma unroll
        for (int nf = 0; nf < 4; ++nf) {
            const int col = bn + wn * 32 + nf * 8 + q2;
            const float b0 = bias[col], b1 = bias[col + 1];
            const float v00 = acc[mf][nf][0] + b0, v01 = acc[mf][nf][1] + b1;
            const float v10 = acc[mf][nf][2] + b0, v11 = acc[mf][nf][3] + b1;
            if (Chi) {
                uint32_t hh, ll;
                hilo2(v00, v01, hh, ll);
                *(uint32_t*)&Chi[(size_t)r0 * Ntot + col] = hh;
                *(uint32_t*)&Clo[(size_t)r0 * Ntot + col] = ll;
                hilo2(v10, v11, hh, ll);
                *(uint32_t*)&Chi[(size_t)(r0 + 8) * Ntot + col] = hh;
                *(uint32_t*)&Clo[(size_t)(r0 + 8) * Ntot + col] = ll;
            } else {
                *(float2*)&Cf[(size_t)r0 * Ntot + col]       = make_float2(v00, v01);
                *(float2*)&Cf[(size_t)(r0 + 8) * Ntot + col] = make_float2(v10, v11);
            }
        }
    }
}

// ---------------------------------------------------------------------------
// Flash attention: Q/K/V read as bf16 hi/lo via cp.async into swizzled smem,
// K/V double-buffered behind compute. Softmax scale folded into exp.
// SMEM: Qh 0, Ql 16K; KV stages at 32K / 64K: Kh,Kl,Vh,Vl (8KB each). 96KB.
// ---------------------------------------------------------------------------
#define FQ_H 0
#define FQ_L 16384
#define FKV0 32768
#define FKV_STG 32768
#define FLASH_SMEM 98304

__global__ __launch_bounds__(256, 2)
void flash_mma()
{
    const int rb = blockIdx.x;          // 0..7
    const int pp = blockIdx.y;
    const int bt = pp >> 3, h = pp & 7;
    extern __shared__ char sm[];
    const uint32_t sb = smem_u32(sm);
    const int t = threadIdx.x, lane = t & 31, w = t >> 5;
    const size_t base = (size_t)bt * NTOK * QKV_COLS;

    // loader mapping: idx -> (row, blk) over 64Bx... rows x 8 blocks of 16B
    const int lrow0 = t >> 3,         lblk0 = t & 7;          // idx t
    const int lrow1 = (t + 256) >> 3, lblk1 = (t + 256) & 7;  // idx t+256
    const uint32_t kvd0 = (uint32_t)(lrow0 * 128 + ((lblk0 ^ (lrow0 & 7)) * 16));
    const uint32_t kvd1 = (uint32_t)(lrow1 * 128 + ((lblk1 ^ (lrow1 & 7)) * 16));

    // ---- prologue: Q (128 rows) + KV tile 0, one commit group ----
    {
        #pragma unroll
        for (int i = 0; i < 4; ++i) {
            const int idx = t + i * 256;
            const int row = idx >> 3, blk = idx & 7;
            const uint32_t d = (uint32_t)(row * 128 + ((blk ^ (row & 7)) * 16));
            const size_t src = base + (size_t)(rb * 128 + row) * QKV_COLS + h * HD + blk * 8;
            cp_async16(sb + FQ_H + d, g_qkvh + src);
            cp_async16(sb + FQ_L + d, g_qkvl + src);
        }
        const size_t k0 = base + (size_t)lrow0 * QKV_COLS + DMODEL + h * HD + lblk0 * 8;
        const size_t k1 = base + (size_t)lrow1 * QKV_COLS + DMODEL + h * HD + lblk1 * 8;
        const uint32_t st = sb + FKV0;
        cp_async16(st + kvd0,         g_qkvh + k0);
        cp_async16(st + kvd1,         g_qkvh + k1);
        cp_async16(st + 8192 + kvd0,  g_qkvl + k0);
        cp_async16(st + 8192 + kvd1,  g_qkvl + k1);
        cp_async16(st + 16384 + kvd0, g_qkvh + k0 + DMODEL);
        cp_async16(st + 16384 + kvd1, g_qkvh + k1 + DMODEL);
        cp_async16(st + 24576 + kvd0, g_qkvl + k0 + DMODEL);
        cp_async16(st + 24576 + kvd1, g_qkvl + k1 + DMODEL);
        CP_COMMIT();
    }

    float s_m0 = -1e30f, s_m1 = -1e30f, s_l0 = 0.f, s_l1 = 0.f;
    float o[8][4];
    #pragma unroll
    for (int nf = 0; nf < 8; ++nf)
        #pragma unroll
        for (int i = 0; i < 4; ++i) o[nf][i] = 0.f;

    const int g = lane >> 2, q2 = (lane & 3) * 2;
    const float SC = 0.125f;   // 1/sqrt(64)

    for (int kb = 0; kb < 16; ++kb) {
        CP_WAIT(0);
        __syncthreads();

        if (kb + 1 < 16) {   // prefetch next KV tile into other stage
            const int r = (kb + 1) * 64;
            const size_t k0 = base + (size_t)(r + lrow0) * QKV_COLS + DMODEL + h * HD + lblk0 * 8;
            const size_t k1 = base + (size_t)(r + lrow1) * QKV_COLS + DMODEL + h * HD + lblk1 * 8;
            const uint32_t st = sb + FKV0 + ((kb + 1) & 1) * FKV_STG;
            cp_async16(st + kvd0,         g_qkvh + k0);
            cp_async16(st + kvd1,         g_qkvh + k1);
            cp_async16(st + 8192 + kvd0,  g_qkvl + k0);
            cp_async16(st + 8192 + kvd1,  g_qkvl + k1);
            cp_async16(st + 16384 + kvd0, g_qkvh + k0 + DMODEL);
            cp_async16(st + 16384 + kvd1, g_qkvh + k1 + DMODEL);
            cp_async16(st + 24576 + kvd0, g_qkvl + k0 + DMODEL);
            cp_async16(st + 24576 + kvd1, g_qkvl + k1 + DMODEL);
            CP_COMMIT();
        }

        const uint32_t kH = sb + FKV0 + (kb & 1) * FKV_STG;
        const uint32_t kL = kH + 8192;
        const uint32_t vH = kH + 16384;
        const uint32_t vL = kH + 24576;

        // ---- S = Q @ K^T (raw, unscaled) ----
        float s[8][4];
        #pragma unroll
        for (int nf = 0; nf < 8; ++nf)
            #pragma unroll
            for (int i = 0; i < 4; ++i) s[nf][i] = 0.f;

        #pragma unroll
        for (int ks = 0; ks < 4; ++ks) {
            uint32_t ah[4], al[4];
            {
                const uint32_t r   = w * 16 + ((lane >> 3) & 1) * 8 + (lane & 7);
                const uint32_t blk = 2 * ks + (lane >> 4);
                const uint32_t off = r * 128 + ((blk ^ (r & 7)) * 16);
                ldsm4(ah, sb + FQ_H + off);
                ldsm4(al, sb + FQ_L + off);
            }
            #pragma unroll
            for (int j = 0; j < 4; ++j) {
                uint32_t bh[4], bl[4];
                const uint32_t key = j * 16 + (lane >> 4) * 8 + (lane & 7);
                const uint32_t blk = 2 * ks + ((lane >> 3) & 1);
                const uint32_t off = key * 128 + ((blk ^ (key & 7)) * 16);
                ldsm4(bh, kH + off);
                ldsm4(bl, kL + off);
                mma16816(s[2 * j],     ah, &bh[0]);
                mma16816(s[2 * j],     ah, &bl[0]);
                mma16816(s[2 * j],     al, &bh[0]);
                mma16816(s[2 * j + 1], ah, &bh[2]);
                mma16816(s[2 * j + 1], ah, &bl[2]);
                mma16816(s[2 * j + 1], al, &bh[2]);
            }
        }

        // ---- online softmax (logical logit = SC * s_raw) ----
        float mt0 = -1e30f, mt1 = -1e30f;
        #pragma unroll
        for (int nf = 0; nf < 8; ++nf) {
            mt0 = fmaxf(mt0, fmaxf(s[nf][0], s[nf][1]));
            mt1 = fmaxf(mt1, fmaxf(s[nf][2], s[nf][3]));
        }
        mt0 = fmaxf(mt0, __shfl_xor_sync(0xffffffffu, mt0, 1));
        mt0 = fmaxf(mt0, __shfl_xor_sync(0xffffffffu, mt0, 2));
        mt1 = fmaxf(mt1, __shfl_xor_sync(0xffffffffu, mt1, 1));
        mt1 = fmaxf(mt1, __shfl_xor_sync(0xffffffffu, mt1, 2));

        const float mn0 = fmaxf(s_m0, mt0), mn1 = fmaxf(s_m1, mt1);
        const float c0 = __expf((s_m0 - mn0) * SC), c1 = __expf((s_m1 - mn1) * SC);
        s_m0 = mn0; s_m1 = mn1;
        const float mo0 = mn0 * SC, mo1 = mn1 * SC;

        float ps0 = 0.f, ps1 = 0.f;
        #pragma unroll
        for (int nf = 0; nf < 8; ++nf) {
            s[nf][0] = __expf(fmaf(s[nf][0], SC, -mo0));
            s[nf][1] = __expf(fmaf(s[nf][1], SC, -mo0));
            s[nf][2] = __expf(fmaf(s[nf][2], SC, -mo1));
            s[nf][3] = __expf(fmaf(s[nf][3], SC, -mo1));
            ps0 += s[nf][0] + s[nf][1];
            ps1 += s[nf][2] + s[nf][3];
        }
        ps0 += __shfl_xor_sync(0xffffffffu, ps0, 1);
        ps0 += __shfl_xor_sync(0xffffffffu, ps0, 2);
        ps1 += __shfl_xor_sync(0xffffffffu, ps1, 1);
        ps1 += __shfl_xor_sync(0xffffffffu, ps1, 2);
        s_l0 = s_l0 * c0 + ps0;
        s_l1 = s_l1 * c1 + ps1;

        #pragma unroll
        for (int nf = 0; nf < 8; ++nf) {
            o[nf][0] *= c0; o[nf][1] *= c0;
            o[nf][2] *= c1; o[nf][3] *= c1;
        }

        // ---- O += P @ V ----
        #pragma unroll
        for (int ks = 0; ks < 4; ++ks) {
            uint32_t ph[4], pl[4];
            hilo2(s[2 * ks][0],     s[2 * ks][1],     ph[0], pl[0]);
            hilo2(s[2 * ks][2],     s[2 * ks][3],     ph[1], pl[1]);
            hilo2(s[2 * ks + 1][0], s[2 * ks + 1][1], ph[2], pl[2]);
            hilo2(s[2 * ks + 1][2], s[2 * ks + 1][3], ph[3], pl[3]);
            #pragma unroll
            for (int j = 0; j < 4; ++j) {
                uint32_t vh[4], vl[4];
                const uint32_t key = ks * 16 + ((lane >> 3) & 1) * 8 + (lane & 7);
                const uint32_t blk = 2 * j + (lane >> 4);
                const uint32_t off = key * 128 + ((blk ^ (key & 7)) * 16);
                ldsm4t(vh, vH + off);
                ldsm4t(vl, vL + off);
                mma16816(o[2 * j],     ph, &vh[0]);
                mma16816(o[2 * j],     ph, &vl[0]);
                mma16816(o[2 * j],     pl, &vh[0]);
                mma16816(o[2 * j + 1], ph, &vh[2]);
                mma16816(o[2 * j + 1], ph, &vl[2]);
                mma16816(o[2 * j + 1], pl, &vh[2]);
            }
        }
    }

    // ---- epilogue ----
    const float inv0 = 1.0f / s_l0, inv1 = 1.0f / s_l1;
    const size_t row0 = (size_t)bt * NTOK + rb * 128 + w * 16 + g;
    const size_t row1 = row0 + 8;
    #pragma unroll
    for (int nf = 0; nf < 8; ++nf) {
        const int col = h * HD + nf * 8 + q2;
        uint32_t hh, ll;
        hilo2(o[nf][0] * inv0, o[nf][1] * inv0, hh, ll);
        *(uint32_t*)&g_attn_hi[row0 * DMODEL + col] = hh;
        *(uint32_t*)&g_attn_lo[row0 * DMODEL + col] = ll;
        hilo2(o[nf][2] * inv1, o[nf][3] * inv1, hh, ll);
        *(uint32_t*)&g_attn_hi[row1 * DMODEL + col] = hh;
        *(uint32_t*)&g_attn_lo[row1 * DMODEL + col] = ll;
    }
}

// ---------------------------------------------------------------------------
extern "C" void kernel_launch(void* const* d_in, const int* in_sizes, int n_in,
                              void* d_out, int out_size)
{
    const float* x      = (const float*)d_in[0];
    const float* W_qkv  = (const float*)d_in[1];
    const float* b_qkv  = (const float*)d_in[2];
    const float* W_proj = (const float*)d_in[3];
    const float* b_proj = (const float*)d_in[4];
    float* out = (float*)d_out;

    void *pqh, *pql, *pxh, *pxl, *pwqh, *pwql, *pwph, *pwpl, *pah, *pal;
    cudaGetSymbolAddress(&pqh, g_qkvh);    cudaGetSymbolAddress(&pql, g_qkvl);
    cudaGetSymbolAddress(&pxh, g_x_hi);    cudaGetSymbolAddress(&pxl, g_x_lo);
    cudaGetSymbolAddress(&pwqh, g_wqt_hi); cudaGetSymbolAddress(&pwql, g_wqt_lo);
    cudaGetSymbolAddress(&pwph, g_wpt_hi); cudaGetSymbolAddress(&pwpl, g_wpt_lo);
    cudaGetSymbolAddress(&pah, g_attn_hi); cudaGetSymbolAddress(&pal, g_attn_lo);

    cudaFuncSetAttribute(gemm_mma,
                         cudaFuncAttributeMaxDynamicSharedMemorySize, GEMM_SMEM);
    cudaFuncSetAttribute(flash_mma,
                         cudaFuncAttributeMaxDynamicSharedMemorySize, FLASH_SMEM);

    // K0a: split x
    {
        const int n4 = MROWS * DMODEL / 4;
        cvt_hilo<<<(n4 + 255) / 256, 256>>>(x, (__nv_bfloat16*)pxh,
                                            (__nv_bfloat16*)pxl, n4);
    }
    // K0b: transpose + split weights
    {
        dim3 blk(32, 8);
        transpose_cvt<<<dim3(QKV_COLS / 32, DMODEL / 32), blk>>>(
            W_qkv, (__nv_bfloat16*)pwqh, (__nv_bfloat16*)pwql, DMODEL, QKV_COLS);
        transpose_cvt<<<dim3(DMODEL / 32, DMODEL / 32), blk>>>(
            W_proj, (__nv_bfloat16*)pwph, (__nv_bfloat16*)pwpl, DMODEL, DMODEL);
    }
    // K1: qkv projection -> bf16 hi/lo
    {
        dim3 grid(QKV_COLS / 256, MROWS / 128);
        gemm_mma<<<grid, 512, GEMM_SMEM>>>(
            (const __nv_bfloat16*)pxh, (const __nv_bfloat16*)pxl,
            (const __nv_bfloat16*)pwqh, (const __nv_bfloat16*)pwql,
            b_qkv, nullptr,
            (__nv_bfloat16*)pqh, (__nv_bfloat16*)pql, QKV_COLS);
    }
    // K2: flash attention
    {
        dim3 grid(NTOK / 128, BT_TOTAL * NHEADS);
        flash_mma<<<grid, 256, FLASH_SMEM>>>();
    }
    // K3: output projection -> fp32 out
    {
        dim3 grid(DMODEL / 256, MROWS / 128);
        gemm_mma<<<grid, 512, GEMM_SMEM>>>(
            (const __nv_bfloat16*)pah, (const __nv_bfloat16*)pal,
            (const __nv_bfloat16*)pwph, (const __nv_bfloat16*)pwpl,
            b_proj, out, nullptr, nullptr, DMODEL);
    }
}

// round 5
// speedup vs baseline: 3.0369x; 1.0007x over previous
#include <cuda_runtime.h>
#include <cuda_bf16.h>
#include <cstdint>

// ---------------------------------------------------------------------------
// SpatialAttention on GB300 (sm_103, mma.sync HMMA path)
//   K1 : qkv_hi/lo = x @ W_qkv + b_qkv   (split-bf16 mma GEMM, bf16 hi/lo out)
//   K2 : flash attention (cp.async bf16 tiles, frag softmax, hi/lo out)
//   K3 : out = attn @ W_proj + b_proj    (split-bf16 mma GEMM, fp32 out)
// Round 5: dependency-chain relief — split-term MMAs issued in separated
// passes so each accumulator's 3 updates have >=15 independent MMAs between.
// ---------------------------------------------------------------------------

#define BT_TOTAL 16
#define NTOK     1024
#define DMODEL   512
#define NHEADS   8
#define HD       64
#define MROWS    (BT_TOTAL * NTOK)      // 16384
#define QKV_COLS (3 * DMODEL)           // 1536
#define KDIM     512

__device__ __nv_bfloat16  g_qkvh[(size_t)MROWS * QKV_COLS];
__device__ __nv_bfloat16  g_qkvl[(size_t)MROWS * QKV_COLS];
__device__ __nv_bfloat16  g_x_hi[(size_t)MROWS * DMODEL];
__device__ __nv_bfloat16  g_x_lo[(size_t)MROWS * DMODEL];
__device__ __nv_bfloat16  g_wqt_hi[(size_t)QKV_COLS * DMODEL];
__device__ __nv_bfloat16  g_wqt_lo[(size_t)QKV_COLS * DMODEL];
__device__ __nv_bfloat16  g_wpt_hi[(size_t)DMODEL * DMODEL];
__device__ __nv_bfloat16  g_wpt_lo[(size_t)DMODEL * DMODEL];
__device__ __nv_bfloat16  g_attn_hi[(size_t)MROWS * DMODEL];
__device__ __nv_bfloat16  g_attn_lo[(size_t)MROWS * DMODEL];

// ---------------------------------------------------------------------------
// helpers
// ---------------------------------------------------------------------------
__device__ __forceinline__ uint32_t smem_u32(const void* p) {
    uint32_t a;
    asm("{ .reg .u64 t; cvta.to.shared.u64 t, %1; cvt.u32.u64 %0, t; }"
        : "=r"(a) : "l"(p));
    return a;
}
__device__ __forceinline__ void ldsm4(uint32_t* r, uint32_t a) {
    asm volatile("ldmatrix.sync.aligned.m8n8.x4.shared.b16 {%0,%1,%2,%3}, [%4];"
        : "=r"(r[0]), "=r"(r[1]), "=r"(r[2]), "=r"(r[3]) : "r"(a));
}
__device__ __forceinline__ void ldsm4t(uint32_t* r, uint32_t a) {
    asm volatile("ldmatrix.sync.aligned.m8n8.x4.trans.shared.b16 {%0,%1,%2,%3}, [%4];"
        : "=r"(r[0]), "=r"(r[1]), "=r"(r[2]), "=r"(r[3]) : "r"(a));
}
__device__ __forceinline__ void mma16816(float* d, const uint32_t* a, const uint32_t* b) {
    asm volatile("mma.sync.aligned.m16n8k16.row.col.f32.bf16.bf16.f32 "
        "{%0,%1,%2,%3},{%4,%5,%6,%7},{%8,%9},{%0,%1,%2,%3};"
        : "+f"(d[0]), "+f"(d[1]), "+f"(d[2]), "+f"(d[3])
        : "r"(a[0]), "r"(a[1]), "r"(a[2]), "r"(a[3]), "r"(b[0]), "r"(b[1]));
}
__device__ __forceinline__ void cp_async16(uint32_t s, const void* g) {
    asm volatile("cp.async.cg.shared.global [%0], [%1], 16;" :: "r"(s), "l"(g));
}
#define CP_COMMIT() asm volatile("cp.async.commit_group;")
#define CP_WAIT(n)  asm volatile("cp.async.wait_group %0;" :: "n"(n) : "memory")

__device__ __forceinline__ void hilo2(float a, float b, uint32_t& h, uint32_t& l) {
    __nv_bfloat162 hb = __floats2bfloat162_rn(a, b);
    float2 hf = __bfloat1622float2(hb);
    __nv_bfloat162 lb = __floats2bfloat162_rn(a - hf.x, b - hf.y);
    h = *(uint32_t*)&hb;
    l = *(uint32_t*)&lb;
}

// ---------------------------------------------------------------------------
// prep kernels
// ---------------------------------------------------------------------------
__global__ void cvt_hilo(const float* __restrict__ X, __nv_bfloat16* __restrict__ H,
                         __nv_bfloat16* __restrict__ L, int n4)
{
    int i = blockIdx.x * blockDim.x + threadIdx.x;
    if (i >= n4) return;
    float4 v = ((const float4*)X)[i];
    uint32_t h0, l0, h1, l1;
    hilo2(v.x, v.y, h0, l0);
    hilo2(v.z, v.w, h1, l1);
    ((uint32_t*)H)[i * 2 + 0] = h0;
    ((uint32_t*)H)[i * 2 + 1] = h1;
    ((uint32_t*)L)[i * 2 + 0] = l0;
    ((uint32_t*)L)[i * 2 + 1] = l1;
}

__global__ void transpose_cvt(const float* __restrict__ W, __nv_bfloat16* __restrict__ Th,
                              __nv_bfloat16* __restrict__ Tl, int K, int N)
{
    __shared__ float tile[32][33];
    const int bx = blockIdx.x * 32;
    const int by = blockIdx.y * 32;
    const int tx = threadIdx.x, ty = threadIdx.y;
    #pragma unroll
    for (int i = 0; i < 32; i += 8)
        tile[ty + i][tx] = W[(size_t)(by + ty + i) * N + bx + tx];
    __syncthreads();
    #pragma unroll
    for (int i = 0; i < 32; i += 8) {
        float v = tile[tx][ty + i];
        size_t o = (size_t)(bx + ty + i) * K + by + tx;
        __nv_bfloat16 h = __float2bfloat16(v);
        Th[o] = h;
        Tl[o] = __float2bfloat16(v - __bfloat162float(h));
    }
}

// ---------------------------------------------------------------------------
// split-bf16 GEMM: CTA 128x256, 512 threads (16 warps, warp tile 64x32),
// k-chunk 32, 3-stage cp.async pipeline. 80B-padded rows (LDSM conflict-free).
// MMA issue order: pass1 all hi*hi, pass2 all hi*lo, pass3 all lo*hi.
// ---------------------------------------------------------------------------
#define GROWB 80
#define G_A   (128 * GROWB)
#define G_B   (256 * GROWB)
#define GSTG  (2 * G_A + 2 * G_B)
#define GEMM_SMEM (3 * GSTG)

__global__ __launch_bounds__(512, 1)
void gemm_mma(const __nv_bfloat16* __restrict__ Ah, const __nv_bfloat16* __restrict__ Al,
              const __nv_bfloat16* __restrict__ Bh, const __nv_bfloat16* __restrict__ Bl,
              const float* __restrict__ bias, float* __restrict__ Cf,
              __nv_bfloat16* __restrict__ Chi, __nv_bfloat16* __restrict__ Clo, int Ntot)
{
    extern __shared__ char sm[];
    const uint32_t sb = smem_u32(sm);
    const int t = threadIdx.x, lane = t & 31, w = t >> 5;
    const int wm = w >> 3, wn = w & 7;
    const int bm = blockIdx.y * 128, bn = blockIdx.x * 256;

    const int arow = t >> 2, ablk = t & 3;
    const __nv_bfloat16* pAh = Ah + (size_t)(bm + arow) * KDIM + ablk * 8;
    const __nv_bfloat16* pAl = Al + (size_t)(bm + arow) * KDIM + ablk * 8;
    const uint32_t adst = (uint32_t)(arow * GROWB + ablk * 16);
    const int brow0 = t >> 2, brow1 = (t + 512) >> 2;
    const int bblk0 = t & 3,  bblk1 = (t + 512) & 3;
    const __nv_bfloat16* pBh0 = Bh + (size_t)(bn + brow0) * KDIM + bblk0 * 8;
    const __nv_bfloat16* pBh1 = Bh + (size_t)(bn + brow1) * KDIM + bblk1 * 8;
    const __nv_bfloat16* pBl0 = Bl + (size_t)(bn + brow0) * KDIM + bblk0 * 8;
    const __nv_bfloat16* pBl1 = Bl + (size_t)(bn + brow1) * KDIM + bblk1 * 8;
    const uint32_t bdst0 = (uint32_t)(brow0 * GROWB + bblk0 * 16);
    const uint32_t bdst1 = (uint32_t)(brow1 * GROWB + bblk1 * 16);

    float acc[4][4][4];
    #pragma unroll
    for (int a = 0; a < 4; ++a)
        #pragma unroll
        for (int b = 0; b < 4; ++b)
            #pragma unroll
            for (int c = 0; c < 4; ++c) acc[a][b][c] = 0.f;

    #pragma unroll
    for (int c = 0; c < 2; ++c) {
        const int koff = c * 32;
        const uint32_t st = sb + c * GSTG;
        cp_async16(st + adst,                  pAh + koff);
        cp_async16(st + G_A + adst,            pAl + koff);
        cp_async16(st + 2 * G_A + bdst0,       pBh0 + koff);
        cp_async16(st + 2 * G_A + bdst1,       pBh1 + koff);
        cp_async16(st + 2 * G_A + G_B + bdst0, pBl0 + koff);
        cp_async16(st + 2 * G_A + G_B + bdst1, pBl1 + koff);
        CP_COMMIT();
    }

    int stg = 0;
    for (int c = 0; c < 16; ++c) {
        if (c < 14) CP_WAIT(1); else CP_WAIT(0);
        __syncthreads();

        if (c + 2 < 16) {
            const int koff = (c + 2) * 32;
            const int s2 = (stg + 2 == 3) ? 0 : ((stg + 2 == 4) ? 1 : stg + 2);
            const uint32_t st = sb + s2 * GSTG;
            cp_async16(st + adst,                  pAh + koff);
            cp_async16(st + G_A + adst,            pAl + koff);
            cp_async16(st + 2 * G_A + bdst0,       pBh0 + koff);
            cp_async16(st + 2 * G_A + bdst1,       pBh1 + koff);
            cp_async16(st + 2 * G_A + G_B + bdst0, pBl0 + koff);
            cp_async16(st + 2 * G_A + G_B + bdst1, pBl1 + koff);
            CP_COMMIT();
        }

        const uint32_t aH = sb + stg * GSTG;
        const uint32_t aL = aH + G_A;
        const uint32_t bH = aH + 2 * G_A;
        const uint32_t bL = bH + G_B;

        #pragma unroll
        for (int ks = 0; ks < 2; ++ks) {
            // fragment loads first
            uint32_t bh[2][4], bl[2][4];
            #pragma unroll
            for (int j = 0; j < 2; ++j) {
                const uint32_t n   = wn * 32 + j * 16 + (lane >> 4) * 8 + (lane & 7);
                const uint32_t blk = 2 * ks + ((lane >> 3) & 1);
                ldsm4(bh[j], bH + n * GROWB + blk * 16);
                ldsm4(bl[j], bL + n * GROWB + blk * 16);
            }
            uint32_t ah[4][4];
            const uint32_t rbase = wm * 64 + ((lane >> 3) & 1) * 8 + (lane & 7);
            const uint32_t ablk2 = 2 * ks + (lane >> 4);
            #pragma unroll
            for (int mf = 0; mf < 4; ++mf)
                ldsm4(ah[mf], aH + (rbase + mf * 16) * GROWB + ablk2 * 16);

            // pass 1: hi * hi  (16 independent MMAs)
            #pragma unroll
            for (int mf = 0; mf < 4; ++mf)
                #pragma unroll
                for (int nf = 0; nf < 4; ++nf)
                    mma16816(acc[mf][nf], ah[mf], &bh[nf >> 1][(nf & 1) * 2]);
            // pass 2: hi * lo
            #pragma unroll
            for (int mf = 0; mf < 4; ++mf)
                #pragma unroll
                for (int nf = 0; nf < 4; ++nf)
                    mma16816(acc[mf][nf], ah[mf], &bl[nf >> 1][(nf & 1) * 2]);
            // pass 3: lo * hi (al loaded per-mf, 4 independent MMAs follow)
            #pragma unroll
            for (int mf = 0; mf < 4; ++mf) {
                uint32_t al[4];
                ldsm4(al, aL + (rbase + mf * 16) * GROWB + ablk2 * 16);
                #pragma unroll
                for (int nf = 0; nf < 4; ++nf)
                    mma16816(acc[mf][nf], al, &bh[nf >> 1][(nf & 1) * 2]);
            }
        }
        stg = (stg == 2) ? 0 : stg + 1;
    }

    const int g = lane >> 2, q2 = (lane & 3) * 2;
    #pragma unroll
    for (int mf = 0; mf < 4; ++mf) {
        const int r0 = bm + wm * 64 + mf * 16 + g;
        #pragma unroll
        for (int nf = 0; nf < 4; ++nf) {
            const int col = bn + wn * 32 + nf * 8 + q2;
            const float b0 = bias[col], b1 = bias[col + 1];
            const float v00 = acc[mf][nf][0] + b0, v01 = acc[mf][nf][1] + b1;
            const float v10 = acc[mf][nf][2] + b0, v11 = acc[mf][nf][3] + b1;
            if (Chi) {
                uint32_t hh, ll;
                hilo2(v00, v01, hh, ll);
                *(uint32_t*)&Chi[(size_t)r0 * Ntot + col] = hh;
                *(uint32_t*)&Clo[(size_t)r0 * Ntot + col] = ll;
                hilo2(v10, v11, hh, ll);
                *(uint32_t*)&Chi[(size_t)(r0 + 8) * Ntot + col] = hh;
                *(uint32_t*)&Clo[(size_t)(r0 + 8) * Ntot + col] = ll;
            } else {
                *(float2*)&Cf[(size_t)r0 * Ntot + col]       = make_float2(v00, v01);
                *(float2*)&Cf[(size_t)(r0 + 8) * Ntot + col] = make_float2(v10, v11);
            }
        }
    }
}

// ---------------------------------------------------------------------------
// Flash attention: bf16 hi/lo via cp.async, double-buffered KV, frag softmax.
// MMA triples issued in separated passes (j unrolled by 2 -> 4 indep chains).
// ---------------------------------------------------------------------------
#define FQ_H 0
#define FQ_L 16384
#define FKV0 32768
#define FKV_STG 32768
#define FLASH_SMEM 98304

__global__ __launch_bounds__(256, 2)
void flash_mma()
{
    const int rb = blockIdx.x;
    const int pp = blockIdx.y;
    const int bt = pp >> 3, h = pp & 7;
    extern __shared__ char sm[];
    const uint32_t sb = smem_u32(sm);
    const int t = threadIdx.x, lane = t & 31, w = t >> 5;
    const size_t base = (size_t)bt * NTOK * QKV_COLS;

    const int lrow0 = t >> 3,         lblk0 = t & 7;
    const int lrow1 = (t + 256) >> 3, lblk1 = (t + 256) & 7;
    const uint32_t kvd0 = (uint32_t)(lrow0 * 128 + ((lblk0 ^ (lrow0 & 7)) * 16));
    const uint32_t kvd1 = (uint32_t)(lrow1 * 128 + ((lblk1 ^ (lrow1 & 7)) * 16));

    {
        #pragma unroll
        for (int i = 0; i < 4; ++i) {
            const int idx = t + i * 256;
            const int row = idx >> 3, blk = idx & 7;
            const uint32_t d = (uint32_t)(row * 128 + ((blk ^ (row & 7)) * 16));
            const size_t src = base + (size_t)(rb * 128 + row) * QKV_COLS + h * HD + blk * 8;
            cp_async16(sb + FQ_H + d, g_qkvh + src);
            cp_async16(sb + FQ_L + d, g_qkvl + src);
        }
        const size_t k0 = base + (size_t)lrow0 * QKV_COLS + DMODEL + h * HD + lblk0 * 8;
        const size_t k1 = base + (size_t)lrow1 * QKV_COLS + DMODEL + h * HD + lblk1 * 8;
        const uint32_t st = sb + FKV0;
        cp_async16(st + kvd0,         g_qkvh + k0);
        cp_async16(st + kvd1,         g_qkvh + k1);
        cp_async16(st + 8192 + kvd0,  g_qkvl + k0);
        cp_async16(st + 8192 + kvd1,  g_qkvl + k1);
        cp_async16(st + 16384 + kvd0, g_qkvh + k0 + DMODEL);
        cp_async16(st + 16384 + kvd1, g_qkvh + k1 + DMODEL);
        cp_async16(st + 24576 + kvd0, g_qkvl + k0 + DMODEL);
        cp_async16(st + 24576 + kvd1, g_qkvl + k1 + DMODEL);
        CP_COMMIT();
    }

    float s_m0 = -1e30f, s_m1 = -1e30f, s_l0 = 0.f, s_l1 = 0.f;
    float o[8][4];
    #pragma unroll
    for (int nf = 0; nf < 8; ++nf)
        #pragma unroll
        for (int i = 0; i < 4; ++i) o[nf][i] = 0.f;

    const int g = lane >> 2, q2 = (lane & 3) * 2;
    const float SC = 0.125f;

    for (int kb = 0; kb < 16; ++kb) {
        CP_WAIT(0);
        __syncthreads();

        if (kb + 1 < 16) {
            const int r = (kb + 1) * 64;
            const size_t k0 = base + (size_t)(r + lrow0) * QKV_COLS + DMODEL + h * HD + lblk0 * 8;
            const size_t k1 = base + (size_t)(r + lrow1) * QKV_COLS + DMODEL + h * HD + lblk1 * 8;
            const uint32_t st = sb + FKV0 + ((kb + 1) & 1) * FKV_STG;
            cp_async16(st + kvd0,         g_qkvh + k0);
            cp_async16(st + kvd1,         g_qkvh + k1);
            cp_async16(st + 8192 + kvd0,  g_qkvl + k0);
            cp_async16(st + 8192 + kvd1,  g_qkvl + k1);
            cp_async16(st + 16384 + kvd0, g_qkvh + k0 + DMODEL);
            cp_async16(st + 16384 + kvd1, g_qkvh + k1 + DMODEL);
            cp_async16(st + 24576 + kvd0, g_qkvl + k0 + DMODEL);
            cp_async16(st + 24576 + kvd1, g_qkvl + k1 + DMODEL);
            CP_COMMIT();
        }

        const uint32_t kH = sb + FKV0 + (kb & 1) * FKV_STG;
        const uint32_t kL = kH + 8192;
        const uint32_t vH = kH + 16384;
        const uint32_t vL = kH + 24576;

        // ---- S = Q @ K^T ----
        float s[8][4];
        #pragma unroll
        for (int nf = 0; nf < 8; ++nf)
            #pragma unroll
            for (int i = 0; i < 4; ++i) s[nf][i] = 0.f;

        #pragma unroll
        for (int ks = 0; ks < 4; ++ks) {
            uint32_t ah[4], al[4];
            {
                const uint32_t r   = w * 16 + ((lane >> 3) & 1) * 8 + (lane & 7);
                const uint32_t blk = 2 * ks + (lane >> 4);
                const uint32_t off = r * 128 + ((blk ^ (r & 7)) * 16);
                ldsm4(ah, sb + FQ_H + off);
                ldsm4(al, sb + FQ_L + off);
            }
            #pragma unroll
            for (int j = 0; j < 4; j += 2) {
                uint32_t bh[2][4], bl[2][4];
                #pragma unroll
                for (int u = 0; u < 2; ++u) {
                    const uint32_t key = (j + u) * 16 + (lane >> 4) * 8 + (lane & 7);
                    const uint32_t blk = 2 * ks + ((lane >> 3) & 1);
                    const uint32_t off = key * 128 + ((blk ^ (key & 7)) * 16);
                    ldsm4(bh[u], kH + off);
                    ldsm4(bl[u], kL + off);
                }
                // pass 1: hi*hi  (4 independent)
                mma16816(s[2 * j],     ah, &bh[0][0]);
                mma16816(s[2 * j + 1], ah, &bh[0][2]);
                mma16816(s[2 * j + 2], ah, &bh[1][0]);
                mma16816(s[2 * j + 3], ah, &bh[1][2]);
                // pass 2: hi*lo
                mma16816(s[2 * j],     ah, &bl[0][0]);
                mma16816(s[2 * j + 1], ah, &bl[0][2]);
                mma16816(s[2 * j + 2], ah, &bl[1][0]);
                mma16816(s[2 * j + 3], ah, &bl[1][2]);
                // pass 3: lo*hi
                mma16816(s[2 * j],     al, &bh[0][0]);
                mma16816(s[2 * j + 1], al, &bh[0][2]);
                mma16816(s[2 * j + 2], al, &bh[1][0]);
                mma16816(s[2 * j + 3], al, &bh[1][2]);
            }
        }

        // ---- online softmax (logit = SC * s_raw) ----
        float mt0 = -1e30f, mt1 = -1e30f;
        #pragma unroll
        for (int nf = 0; nf < 8; ++nf) {
            mt0 = fmaxf(mt0, fmaxf(s[nf][0], s[nf][1]));
            mt1 = fmaxf(mt1, fmaxf(s[nf][2], s[nf][3]));
        }
        mt0 = fmaxf(mt0, __shfl_xor_sync(0xffffffffu, mt0, 1));
        mt0 = fmaxf(mt0, __shfl_xor_sync(0xffffffffu, mt0, 2));
        mt1 = fmaxf(mt1, __shfl_xor_sync(0xffffffffu, mt1, 1));
        mt1 = fmaxf(mt1, __shfl_xor_sync(0xffffffffu, mt1, 2));

        const float mn0 = fmaxf(s_m0, mt0), mn1 = fmaxf(s_m1, mt1);
        const float c0 = __expf((s_m0 - mn0) * SC), c1 = __expf((s_m1 - mn1) * SC);
        s_m0 = mn0; s_m1 = mn1;
        const float mo0 = mn0 * SC, mo1 = mn1 * SC;

        float ps0 = 0.f, ps1 = 0.f;
        #pragma unroll
        for (int nf = 0; nf < 8; ++nf) {
            s[nf][0] = __expf(fmaf(s[nf][0], SC, -mo0));
            s[nf][1] = __expf(fmaf(s[nf][1], SC, -mo0));
            s[nf][2] = __expf(fmaf(s[nf][2], SC, -mo1));
            s[nf][3] = __expf(fmaf(s[nf][3], SC, -mo1));
            ps0 += s[nf][0] + s[nf][1];
            ps1 += s[nf][2] + s[nf][3];
        }
        ps0 += __shfl_xor_sync(0xffffffffu, ps0, 1);
        ps0 += __shfl_xor_sync(0xffffffffu, ps0, 2);
        ps1 += __shfl_xor_sync(0xffffffffu, ps1, 1);
        ps1 += __shfl_xor_sync(0xffffffffu, ps1, 2);
        s_l0 = s_l0 * c0 + ps0;
        s_l1 = s_l1 * c1 + ps1;

        #pragma unroll
        for (int nf = 0; nf < 8; ++nf) {
            o[nf][0] *= c0; o[nf][1] *= c0;
            o[nf][2] *= c1; o[nf][3] *= c1;
        }

        // ---- O += P @ V ----
        #pragma unroll
        for (int ks = 0; ks < 4; ++ks) {
            uint32_t ph[4], pl[4];
            hilo2(s[2 * ks][0],     s[2 * ks][1],     ph[0], pl[0]);
            hilo2(s[2 * ks][2],     s[2 * ks][3],     ph[1], pl[1]);
            hilo2(s[2 * ks + 1][0], s[2 * ks + 1][1], ph[2], pl[2]);
            hilo2(s[2 * ks + 1][2], s[2 * ks + 1][3], ph[3], pl[3]);
            #pragma unroll
            for (int j = 0; j < 4; j += 2) {
                uint32_t vh[2][4], vl[2][4];
                #pragma unroll
                for (int u = 0; u < 2; ++u) {
                    const uint32_t key = ks * 16 + ((lane >> 3) & 1) * 8 + (lane & 7);
                    const uint32_t blk = 2 * (j + u) + (lane >> 4);
                    const uint32_t off = key * 128 + ((blk ^ (key & 7)) * 16);
                    ldsm4t(vh[u], vH + off);
                    ldsm4t(vl[u], vL + off);
                }
                // pass 1: P_hi * V_hi (4 independent)
                mma16816(o[2 * j],     ph, &vh[0][0]);
                mma16816(o[2 * j + 1], ph, &vh[0][2]);
                mma16816(o[2 * j + 2], ph, &vh[1][0]);
                mma16816(o[2 * j + 3], ph, &vh[1][2]);
                // pass 2: P_hi * V_lo
                mma16816(o[2 * j],     ph, &vl[0][0]);
                mma16816(o[2 * j + 1], ph, &vl[0][2]);
                mma16816(o[2 * j + 2], ph, &vl[1][0]);
                mma16816(o[2 * j + 3], ph, &vl[1][2]);
                // pass 3: P_lo * V_hi
                mma16816(o[2 * j],     pl, &vh[0][0]);
                mma16816(o[2 * j + 1], pl, &vh[0][2]);
                mma16816(o[2 * j + 2], pl, &vh[1][0]);
                mma16816(o[2 * j + 3], pl, &vh[1][2]);
            }
        }
    }

    const float inv0 = 1.0f / s_l0, inv1 = 1.0f / s_l1;
    const size_t row0 = (size_t)bt * NTOK + rb * 128 + w * 16 + g;
    const size_t row1 = row0 + 8;
    #pragma unroll
    for (int nf = 0; nf < 8; ++nf) {
        const int col = h * HD + nf * 8 + q2;
        uint32_t hh, ll;
        hilo2(o[nf][0] * inv0, o[nf][1] * inv0, hh, ll);
        *(uint32_t*)&g_attn_hi[row0 * DMODEL + col] = hh;
        *(uint32_t*)&g_attn_lo[row0 * DMODEL + col] = ll;
        hilo2(o[nf][2] * inv1, o[nf][3] * inv1, hh, ll);
        *(uint32_t*)&g_attn_hi[row1 * DMODEL + col] = hh;
        *(uint32_t*)&g_attn_lo[row1 * DMODEL + col] = ll;
    }
}

// ---------------------------------------------------------------------------
extern "C" void kernel_launch(void* const* d_in, const int* in_sizes, int n_in,
                              void* d_out, int out_size)
{
    const float* x      = (const float*)d_in[0];
    const float* W_qkv  = (const float*)d_in[1];
    const float* b_qkv  = (const float*)d_in[2];
    const float* W_proj = (const float*)d_in[3];
    const float* b_proj = (const float*)d_in[4];
    float* out = (float*)d_out;

    void *pqh, *pql, *pxh, *pxl, *pwqh, *pwql, *pwph, *pwpl, *pah, *pal;
    cudaGetSymbolAddress(&pqh, g_qkvh);    cudaGetSymbolAddress(&pql, g_qkvl);
    cudaGetSymbolAddress(&pxh, g_x_hi);    cudaGetSymbolAddress(&pxl, g_x_lo);
    cudaGetSymbolAddress(&pwqh, g_wqt_hi); cudaGetSymbolAddress(&pwql, g_wqt_lo);
    cudaGetSymbolAddress(&pwph, g_wpt_hi); cudaGetSymbolAddress(&pwpl, g_wpt_lo);
    cudaGetSymbolAddress(&pah, g_attn_hi); cudaGetSymbolAddress(&pal, g_attn_lo);

    cudaFuncSetAttribute(gemm_mma,
                         cudaFuncAttributeMaxDynamicSharedMemorySize, GEMM_SMEM);
    cudaFuncSetAttribute(flash_mma,
                         cudaFuncAttributeMaxDynamicSharedMemorySize, FLASH_SMEM);

    {
        const int n4 = MROWS * DMODEL / 4;
        cvt_hilo<<<(n4 + 255) / 256, 256>>>(x, (__nv_bfloat16*)pxh,
                                            (__nv_bfloat16*)pxl, n4);
    }
    {
        dim3 blk(32, 8);
        transpose_cvt<<<dim3(QKV_COLS / 32, DMODEL / 32), blk>>>(
            W_qkv, (__nv_bfloat16*)pwqh, (__nv_bfloat16*)pwql, DMODEL, QKV_COLS);
        transpose_cvt<<<dim3(DMODEL / 32, DMODEL / 32), blk>>>(
            W_proj, (__nv_bfloat16*)pwph, (__nv_bfloat16*)pwpl, DMODEL, DMODEL);
    }
    {
        dim3 grid(QKV_COLS / 256, MROWS / 128);
        gemm_mma<<<grid, 512, GEMM_SMEM>>>(
            (const __nv_bfloat16*)pxh, (const __nv_bfloat16*)pxl,
            (const __nv_bfloat16*)pwqh, (const __nv_bfloat16*)pwql,
            b_qkv, nullptr,
            (__nv_bfloat16*)pqh, (__nv_bfloat16*)pql, QKV_COLS);
    }
    {
        dim3 grid(NTOK / 128, BT_TOTAL * NHEADS);
        flash_mma<<<grid, 256, FLASH_SMEM>>>();
    }
    {
        dim3 grid(DMODEL / 256, MROWS / 128);
        gemm_mma<<<grid, 512, GEMM_SMEM>>>(
            (const __nv_bfloat16*)pah, (const __nv_bfloat16*)pal,
            (const __nv_bfloat16*)pwph, (const __nv_bfloat16*)pwpl,
            b_proj, out, nullptr, nullptr, DMODEL);
    }
}